// round 4
// baseline (speedup 1.0000x reference)
#include <cuda_runtime.h>
#include <math.h>
#include <stdint.h>

#define Kk 256
#define Tt 512
#define NBb 256
#define Vv 4096

#define NT 256
#define NC (NBb/2)      // 128 CTAs, 2 sequences each
#define NS 8            // output states per thread
#define QR 11           // i-pair chunks per state held in registers
#define QS 5            // i-pair chunks per state read from smem

typedef unsigned long long ull;

// ---------------- device scratch ----------------
// Packed A in per-thread order: [ (s*QR+q)*256 + tid ] for regs, [ (s*QS+qq)*256 + tid ] for smem.
__device__ ull  g_Freg[NS*QR*Kk];   // forward  (G[i][j] = expA[i][j])
__device__ ull  g_Fsm [NS*QS*Kk];
__device__ ull  g_Breg[NS*QR*Kk];   // backward (G[j][i] = expA[i][j], i.e. expA^T)
__device__ ull  g_Bsm [NS*QS*Kk];
__device__ float g_Bt[Vv*Kk];       // exp(log_B) transposed: [v][j]
__device__ float g_pi[Kk];

// ---------------- prep ----------------
__global__ void prep_pack(const float* __restrict__ logA, const float* __restrict__ logpi) {
    int idx = blockIdx.x * blockDim.x + threadIdx.x;   // 0 .. 32767
    if (idx < Kk) g_pi[idx] = expf(logpi[idx]);
    if (idx >= NS * 16 * Kk) return;
    int tid = idx & 255;
    int sq  = idx >> 8;              // 0..127
    int s = sq >> 4, q = sq & 15;
    int wv = tid >> 5, lv = tid & 31;
    int j  = lv + 32 * s;            // output state
    int i0 = 32 * wv + 2 * q;        // summation index pair base
    float f0 = expf(logA[i0 * Kk + j]);          // forward: A[i][j]
    float f1 = expf(logA[(i0 + 1) * Kk + j]);
    float b0 = expf(logA[j * Kk + i0]);          // backward: A^T[i][j] = A[j][i]
    float b1 = expf(logA[j * Kk + i0 + 1]);
    ull fv = ((ull)__float_as_uint(f1) << 32) | __float_as_uint(f0);
    ull bv = ((ull)__float_as_uint(b1) << 32) | __float_as_uint(b0);
    if (q < QR) {
        g_Freg[(s*QR + q)*Kk + tid] = fv;
        g_Breg[(s*QR + q)*Kk + tid] = bv;
    } else {
        int qq = q - QR;
        g_Fsm[(s*QS + qq)*Kk + tid] = fv;
        g_Bsm[(s*QS + qq)*Kk + tid] = bv;
    }
}

__global__ void prep_B(const float* __restrict__ logB) {
    int idx = blockIdx.x * blockDim.x + threadIdx.x;   // j*Vv + v (coalesced read)
    if (idx >= Kk*Vv) return;
    int j = idx / Vv, v = idx % Vv;
    g_Bt[v*Kk + j] = expf(logB[idx]);
}

// ---------------- helpers ----------------
__device__ __forceinline__ void ffma2(ull& d, ull a, ull b) {
    asm("fma.rn.f32x2 %0, %1, %2, %0;" : "+l"(d) : "l"(a), "l"(b));
}
__device__ __forceinline__ float pair_sum(ull a, ull b) {
    ull s; asm("add.rn.f32x2 %0, %1, %2;" : "=l"(s) : "l"(a), "l"(b));
    unsigned lo, hi; asm("mov.b64 {%0,%1}, %2;" : "=r"(lo), "=r"(hi) : "l"(s));
    return __uint_as_float(lo) + __uint_as_float(hi);
}
__device__ __forceinline__ void wred2(float& v0, float& v1) {
    #pragma unroll
    for (int o = 16; o; o >>= 1) {
        v0 += __shfl_xor_sync(0xFFFFFFFFu, v0, o);
        v1 += __shfl_xor_sync(0xFFFFFFFFu, v1, o);
    }
}

// split-K dot: warp w sums i in [32w, 32w+32) for this thread's 8 states, both seqs.
__device__ __forceinline__ void do_dot(const ull (&ra)[NS*QR],
                                       const ull* __restrict__ As2,   // shared
                                       const float* __restrict__ es,  // shared [2][Kk]
                                       float* __restrict__ part,      // shared [2][8][256]
                                       int w, int l, int tid) {
    #pragma unroll 1
    for (int seq = 0; seq < 2; seq++) {
        const ulonglong2* ep = reinterpret_cast<const ulonglong2*>(es + seq*Kk + 32*w);
        ull ev[16];
        #pragma unroll
        for (int m = 0; m < 8; m++) { ulonglong2 v = ep[m]; ev[2*m] = v.x; ev[2*m+1] = v.y; }
        #pragma unroll
        for (int s = 0; s < NS; s++) {
            ull a0 = 0, a1 = 0;
            #pragma unroll
            for (int q = 0; q < QR; q++) {
                if (q & 1) ffma2(a1, ra[s*QR + q], ev[q]);
                else       ffma2(a0, ra[s*QR + q], ev[q]);
            }
            #pragma unroll
            for (int qq = 0; qq < QS; qq++) {
                ull av = As2[(s*QS + qq)*Kk + tid];
                if (qq & 1) ffma2(a1, av, ev[QR + qq]);
                else        ffma2(a0, av, ev[QR + qq]);
            }
            part[seq*2048 + w*256 + l + 32*s] = pair_sum(a0, a1);
        }
    }
}

// ---------------- main persistent kernel ----------------
__global__ void __launch_bounds__(NT, 1)
hmm_fb(const int* __restrict__ obs, float* __restrict__ out) {
    extern __shared__ float sm[];
    ull*   As2   = (ull*)sm;                        // NS*QS*Kk u64 (80KB)
    float* es    = (float*)(As2 + NS*QS*Kk);        // [2][Kk]
    float* part  = es + 2*Kk;                       // [2][8][256] = 4096
    float* red   = part + 4096;                     // [2][16]
    int*   obs_s = (int*)(red + 32);                // [2][Tt]

    const int tid = threadIdx.x, w = tid >> 5, l = tid & 31;
    const int n0 = 2*blockIdx.x, n1 = n0 + 1;

    for (int i = tid; i < Tt; i += NT) {
        obs_s[i]      = obs[n0*Tt + i];
        obs_s[Tt + i] = obs[n1*Tt + i];
    }

    ull ra[NS*QR];
    #pragma unroll
    for (int k = 0; k < NS*QR; k++) ra[k] = g_Freg[k*Kk + tid];
    #pragma unroll
    for (int k = 0; k < NS*QS; k++) As2[k*Kk + tid] = g_Fsm[k*Kk + tid];
    __syncthreads();

    float* out0 = out + (size_t)n0*Tt*Kk + tid;
    float* out1 = out + (size_t)n1*Tt*Kk + tid;

    int b = 0;
    float w0, w1;

    // ---- forward init (t = 0) ----
    {
        float pi = g_pi[tid];
        w0 = pi * g_Bt[obs_s[0]  * Kk + tid];
        w1 = pi * g_Bt[obs_s[Tt] * Kk + tid];
        es[tid] = w0; es[Kk + tid] = w1;
        float r0 = w0, r1 = w1; wred2(r0, r1);
        if (!l) { red[w] = r0; red[8 + w] = r1; }
        __syncthreads();
    }

    // ---- forward loop ----
    for (int t = 1; t < Tt; t++) {
        float bb0 = g_Bt[obs_s[t]      * Kk + tid];
        float bb1 = g_Bt[obs_s[Tt + t] * Kk + tid];
        do_dot(ra, As2, es, part, w, l, tid);
        __syncthreads();                                      // partials ready; es fully consumed
        float s0 = 0.f, s1 = 0.f;
        #pragma unroll
        for (int k = 0; k < 8; k++) { s0 += part[k*256 + tid]; s1 += part[2048 + k*256 + tid]; }
        float c0 = 0.f, c1 = 0.f;
        #pragma unroll
        for (int k = 0; k < 8; k++) { c0 += red[b*16 + k]; c1 += red[b*16 + 8 + k]; }
        float r0 = __fdividef(1.f, c0), r1 = __fdividef(1.f, c1);
        out0[(size_t)(t-1)*Kk] = w0 * r0;
        out1[(size_t)(t-1)*Kk] = w1 * r1;
        w0 = s0 * r0 * bb0;
        w1 = s1 * r1 * bb1;
        es[tid] = w0; es[Kk + tid] = w1;
        float p0 = w0, p1 = w1; wred2(p0, p1);
        b ^= 1;
        if (!l) { red[b*16 + w] = p0; red[b*16 + 8 + w] = p1; }
        __syncthreads();
    }
    {   // store p_{T-1}
        float c0 = 0.f, c1 = 0.f;
        #pragma unroll
        for (int k = 0; k < 8; k++) { c0 += red[b*16 + k]; c1 += red[b*16 + 8 + k]; }
        out0[(size_t)(Tt-1)*Kk] = w0 * __fdividef(1.f, c0);
        out1[(size_t)(Tt-1)*Kk] = w1 * __fdividef(1.f, c1);
    }
    __syncthreads();

    // ---- reload A-cache for backward ----
    #pragma unroll
    for (int k = 0; k < NS*QR; k++) ra[k] = g_Breg[k*Kk + tid];
    #pragma unroll
    for (int k = 0; k < NS*QS; k++) As2[k*Kk + tid] = g_Bsm[k*Kk + tid];

    // ---- backward init: y_{T-1} = B[:,o_{T-1}] ----
    b = 0;
    {
        float y0 = g_Bt[obs_s[Tt-1]      * Kk + tid];
        float y1 = g_Bt[obs_s[Tt + Tt-1] * Kk + tid];
        es[tid] = y0; es[Kk + tid] = y1;
        float r0 = y0, r1 = y1; wred2(r0, r1);
        if (!l) { red[w] = r0; red[8 + w] = r1; }
        __syncthreads();
    }

    // ---- backward loop ----
    for (int t = Tt - 2; t >= 0; t--) {
        float p0  = out0[(size_t)t*Kk];                        // prefetch (DRAM latency covered by dot)
        float p1  = out1[(size_t)t*Kk];
        float bb0 = g_Bt[obs_s[t]      * Kk + tid];
        float bb1 = g_Bt[obs_s[Tt + t] * Kk + tid];
        do_dot(ra, As2, es, part, w, l, tid);
        __syncthreads();
        float s0 = 0.f, s1 = 0.f;
        #pragma unroll
        for (int k = 0; k < 8; k++) { s0 += part[k*256 + tid]; s1 += part[2048 + k*256 + tid]; }
        float c0 = 0.f, c1 = 0.f;
        #pragma unroll
        for (int k = 0; k < 8; k++) { c0 += red[b*16 + k]; c1 += red[b*16 + 8 + k]; }
        float r0 = __fdividef(1.f, c0), r1 = __fdividef(1.f, c1);
        float be0 = s0 * r0, be1 = s1 * r1;                    // scaled beta_t
        out0[(size_t)t*Kk] = p0 * be0;                         // unnormalized gamma
        out1[(size_t)t*Kk] = p1 * be1;
        float y0 = be0 * bb0, y1 = be1 * bb1;
        es[tid] = y0; es[Kk + tid] = y1;
        float q0 = y0, q1 = y1; wred2(q0, q1);
        b ^= 1;
        if (!l) { red[b*16 + w] = q0; red[b*16 + 8 + w] = q1; }
        __syncthreads();
    }
}

// ---------------- epilogue: per-(n,t) log-normalize ----------------
__global__ void __launch_bounds__(256)
norm_gamma(float* __restrict__ out) {
    int row  = (blockIdx.x << 3) + (threadIdx.x >> 5);
    int lane = threadIdx.x & 31;
    float4* p = reinterpret_cast<float4*>(out + (size_t)row * Kk);
    float4 v0 = p[lane], v1 = p[lane + 32];
    float s = v0.x + v0.y + v0.z + v0.w + v1.x + v1.y + v1.z + v1.w;
    #pragma unroll
    for (int o = 16; o; o >>= 1) s += __shfl_xor_sync(0xFFFFFFFFu, s, o);
    float lc = __logf(s);
    v0.x = __logf(v0.x) - lc; v0.y = __logf(v0.y) - lc;
    v0.z = __logf(v0.z) - lc; v0.w = __logf(v0.w) - lc;
    v1.x = __logf(v1.x) - lc; v1.y = __logf(v1.y) - lc;
    v1.z = __logf(v1.z) - lc; v1.w = __logf(v1.w) - lc;
    p[lane] = v0; p[lane + 32] = v1;
}

// ---------------- launch ----------------
extern "C" void kernel_launch(void* const* d_in, const int* in_sizes, int n_in,
                              void* d_out, int out_size) {
    const float* log_pi = (const float*)d_in[0];
    const float* log_A  = (const float*)d_in[1];
    const float* log_B  = (const float*)d_in[2];
    const int*   observ = (const int*)  d_in[3];
    float* out = (float*)d_out;

    const int smem_bytes = NS*QS*Kk*8 + (2*Kk + 4096 + 32)*4 + 2*Tt*4;
    cudaFuncSetAttribute(hmm_fb, cudaFuncAttributeMaxDynamicSharedMemorySize, smem_bytes);

    prep_pack<<<(NS*16*Kk + 255)/256, 256>>>(log_A, log_pi);
    prep_B<<<(Kk*Vv + 255)/256, 256>>>(log_B);
    hmm_fb<<<NC, NT, smem_bytes>>>(observ, out);
    norm_gamma<<<(NBb*Tt)/8, 256>>>(out);
}

// round 5
// speedup vs baseline: 2.1926x; 2.1926x over previous
#include <cuda_runtime.h>
#include <math.h>
#include <stdint.h>

#define Kk 256
#define Tt 512
#define NBb 256
#define Vv 4096

#define NT 256
#define NC (NBb/2)      // 128 CTAs, 2 sequences each

// Warp tiling: 8 warps = 2 (state dim, p) x 4 (i dim, q).
// Warp (p,q): states {128p + 32m + lane, m=0..3}, i in [64q, 64q+64).
// Per thread: 4 states x 64 i = 256 A floats = 128 u64 pairs;
//   64 u64 in registers (c=0..15 per state), 64 u64 via smem (c=16..31).

typedef unsigned long long ull;

// ---------------- device scratch ----------------
__device__ ull  g_Freg[64*NT];     // forward  A-pack, register part
__device__ ull  g_Fsm [64*NT];     // forward  A-pack, smem part
__device__ ull  g_Breg[64*NT];     // backward A-pack, register part
__device__ ull  g_Bsm [64*NT];     // backward A-pack, smem part
__device__ float g_Bt[Vv*Kk];      // exp(log_B) transposed: [v][j]
__device__ float g_pi[Kk];

// ---------------- prep ----------------
__global__ void prep_pack(const float* __restrict__ logA, const float* __restrict__ logpi) {
    int idx = blockIdx.x * blockDim.x + threadIdx.x;   // 0 .. 32767
    if (idx < Kk) g_pi[idx] = expf(logpi[idx]);
    int tid = idx & 255;
    int k   = idx >> 8;            // 0..127 : k = m*32 + c
    int m = k >> 5, c = k & 31;
    int wi = tid >> 5, l = tid & 31;
    int p = wi >> 2, q = wi & 3;
    int j = 128*p + 32*m + l;      // output state
    int i = 64*q + 2*c;            // summation index (pair base)
    float f0 = expf(logA[i*Kk + j]);        // fwd: sum_i e[i]*A[i][j]
    float f1 = expf(logA[(i+1)*Kk + j]);
    float b0 = expf(logA[j*Kk + i]);        // bwd: sum_i e[i]*A[j][i]
    float b1 = expf(logA[j*Kk + i + 1]);
    ull fv = ((ull)__float_as_uint(f1) << 32) | __float_as_uint(f0);
    ull bv = ((ull)__float_as_uint(b1) << 32) | __float_as_uint(b0);
    if (c < 16) {
        g_Freg[(m*16 + c)*NT + tid] = fv;
        g_Breg[(m*16 + c)*NT + tid] = bv;
    } else {
        int cc = c - 16;
        int u = (((m*8 + (cc>>1))*NT + tid) << 1) | (cc & 1);  // ulonglong2-friendly
        g_Fsm[u] = fv;
        g_Bsm[u] = bv;
    }
}

__global__ void prep_B(const float* __restrict__ logB) {
    int idx = blockIdx.x * blockDim.x + threadIdx.x;   // j*Vv + v (coalesced read)
    if (idx >= Kk*Vv) return;
    int j = idx / Vv, v = idx % Vv;
    g_Bt[v*Kk + j] = expf(logB[idx]);
}

// ---------------- helpers ----------------
__device__ __forceinline__ void ffma2(ull& d, ull a, ull b) {
    asm("fma.rn.f32x2 %0, %1, %2, %0;" : "+l"(d) : "l"(a), "l"(b));
}
__device__ __forceinline__ float psum1(ull a) {
    unsigned lo, hi; asm("mov.b64 {%0,%1}, %2;" : "=r"(lo), "=r"(hi) : "l"(a));
    return __uint_as_float(lo) + __uint_as_float(hi);
}
__device__ __forceinline__ void wred2(float& v0, float& v1) {
    #pragma unroll
    for (int o = 16; o; o >>= 1) {
        v0 += __shfl_xor_sync(0xFFFFFFFFu, v0, o);
        v1 += __shfl_xor_sync(0xFFFFFFFFu, v1, o);
    }
}

// split-K dot: this warp covers i in [64q,64q+64) for its 4 states, both seqs.
__device__ __forceinline__ void do_dot(const ull (&ra)[64],
                                       const ull* __restrict__ As2,
                                       const float* __restrict__ es,   // [2][Kk]
                                       float* __restrict__ part,       // [2][4][256]
                                       int p, int q, int l, int tid) {
    const ulonglong2* e0 = reinterpret_cast<const ulonglong2*>(es + 64*q);
    const ulonglong2* e1 = reinterpret_cast<const ulonglong2*>(es + Kk + 64*q);
    ull acc[4][2] = {};
    // register half: c = 0..15
    #pragma unroll
    for (int h = 0; h < 8; h++) {
        ulonglong2 v0 = e0[h], v1 = e1[h];
        #pragma unroll
        for (int m = 0; m < 4; m++) {
            ffma2(acc[m][0], ra[m*16 + 2*h],     v0.x);
            ffma2(acc[m][0], ra[m*16 + 2*h + 1], v0.y);
            ffma2(acc[m][1], ra[m*16 + 2*h],     v1.x);
            ffma2(acc[m][1], ra[m*16 + 2*h + 1], v1.y);
        }
    }
    // smem half: c = 16..31
    const ulonglong2* Asv = reinterpret_cast<const ulonglong2*>(As2);
    #pragma unroll
    for (int h = 0; h < 8; h++) {
        ulonglong2 v0 = e0[8 + h], v1 = e1[8 + h];
        #pragma unroll
        for (int m = 0; m < 4; m++) {
            ulonglong2 av = Asv[(m*8 + h)*NT + tid];
            ffma2(acc[m][0], av.x, v0.x);
            ffma2(acc[m][0], av.y, v0.y);
            ffma2(acc[m][1], av.x, v1.x);
            ffma2(acc[m][1], av.y, v1.y);
        }
    }
    #pragma unroll
    for (int m = 0; m < 4; m++) {
        int j = 128*p + 32*m + l;
        part[q*256 + j]        = psum1(acc[m][0]);
        part[1024 + q*256 + j] = psum1(acc[m][1]);
    }
}

// ---------------- main persistent kernel ----------------
__global__ void __launch_bounds__(NT, 1)
hmm_fb(const int* __restrict__ obs, float* __restrict__ out) {
    extern __shared__ float sm[];
    ull*   As2   = (ull*)sm;                    // 64*NT u64 = 128KB
    float* es    = (float*)(As2 + 64*NT);       // [2][Kk]
    float* part  = es + 2*Kk;                   // [2][4][256] = 2048
    float* red   = part + 2048;                 // [2][16]
    int*   obs_s = (int*)(red + 32);            // [2][Tt]

    const int tid = threadIdx.x, wi = tid >> 5, l = tid & 31;
    const int p = wi >> 2, q = wi & 3;
    const int n0 = 2*blockIdx.x, n1 = n0 + 1;

    for (int i = tid; i < Tt; i += NT) {
        obs_s[i]      = obs[n0*Tt + i];
        obs_s[Tt + i] = obs[n1*Tt + i];
    }

    ull ra[64];
    #pragma unroll
    for (int k = 0; k < 64; k++) ra[k] = g_Freg[k*NT + tid];
    {
        const ulonglong2* src = reinterpret_cast<const ulonglong2*>(g_Fsm);
        ulonglong2*       dst = reinterpret_cast<ulonglong2*>(As2);
        #pragma unroll
        for (int k = 0; k < 32; k++) dst[k*NT + tid] = src[k*NT + tid];
    }
    __syncthreads();

    float* out0 = out + (size_t)n0*Tt*Kk + tid;
    float* out1 = out + (size_t)n1*Tt*Kk + tid;

    int b = 0;
    float w0, w1;

    // ---- forward init (t = 0) ----
    {
        float pi = g_pi[tid];
        w0 = pi * g_Bt[obs_s[0]  * Kk + tid];
        w1 = pi * g_Bt[obs_s[Tt] * Kk + tid];
        es[tid] = w0; es[Kk + tid] = w1;
        float r0 = w0, r1 = w1; wred2(r0, r1);
        if (!l) { red[wi] = r0; red[8 + wi] = r1; }
        __syncthreads();
    }

    // ---- forward loop ----
    for (int t = 1; t < Tt; t++) {
        float bb0 = g_Bt[obs_s[t]      * Kk + tid];
        float bb1 = g_Bt[obs_s[Tt + t] * Kk + tid];
        do_dot(ra, As2, es, part, p, q, l, tid);
        __syncthreads();                                   // partials ready
        float s0 = 0.f, s1 = 0.f;
        #pragma unroll
        for (int k = 0; k < 4; k++) { s0 += part[k*256 + tid]; s1 += part[1024 + k*256 + tid]; }
        float c0 = 0.f, c1 = 0.f;
        #pragma unroll
        for (int k = 0; k < 8; k++) { c0 += red[b*16 + k]; c1 += red[b*16 + 8 + k]; }
        float r0 = __fdividef(1.f, c0), r1 = __fdividef(1.f, c1);
        out0[(size_t)(t-1)*Kk] = w0 * r0;
        out1[(size_t)(t-1)*Kk] = w1 * r1;
        w0 = s0 * r0 * bb0;
        w1 = s1 * r1 * bb1;
        es[tid] = w0; es[Kk + tid] = w1;
        float p0 = w0, p1 = w1; wred2(p0, p1);
        b ^= 1;
        if (!l) { red[b*16 + wi] = p0; red[b*16 + 8 + wi] = p1; }
        __syncthreads();                                   // es/red ready for next dot
    }
    {   // store p_{T-1}
        float c0 = 0.f, c1 = 0.f;
        #pragma unroll
        for (int k = 0; k < 8; k++) { c0 += red[b*16 + k]; c1 += red[b*16 + 8 + k]; }
        out0[(size_t)(Tt-1)*Kk] = w0 * __fdividef(1.f, c0);
        out1[(size_t)(Tt-1)*Kk] = w1 * __fdividef(1.f, c1);
    }
    __syncthreads();

    // ---- reload A-pack for backward ----
    #pragma unroll
    for (int k = 0; k < 64; k++) ra[k] = g_Breg[k*NT + tid];
    {
        const ulonglong2* src = reinterpret_cast<const ulonglong2*>(g_Bsm);
        ulonglong2*       dst = reinterpret_cast<ulonglong2*>(As2);
        #pragma unroll
        for (int k = 0; k < 32; k++) dst[k*NT + tid] = src[k*NT + tid];
    }

    // ---- backward init: y_{T-1} = B[:,o_{T-1}] ----
    b = 0;
    {
        float y0 = g_Bt[obs_s[Tt-1]      * Kk + tid];
        float y1 = g_Bt[obs_s[Tt + Tt-1] * Kk + tid];
        es[tid] = y0; es[Kk + tid] = y1;
        float r0 = y0, r1 = y1; wred2(r0, r1);
        if (!l) { red[wi] = r0; red[8 + wi] = r1; }
        __syncthreads();
    }

    // ---- backward loop ----
    for (int t = Tt - 2; t >= 0; t--) {
        float pp0 = out0[(size_t)t*Kk];                    // prefetch
        float pp1 = out1[(size_t)t*Kk];
        float bb0 = g_Bt[obs_s[t]      * Kk + tid];
        float bb1 = g_Bt[obs_s[Tt + t] * Kk + tid];
        do_dot(ra, As2, es, part, p, q, l, tid);
        __syncthreads();
        float s0 = 0.f, s1 = 0.f;
        #pragma unroll
        for (int k = 0; k < 4; k++) { s0 += part[k*256 + tid]; s1 += part[1024 + k*256 + tid]; }
        float c0 = 0.f, c1 = 0.f;
        #pragma unroll
        for (int k = 0; k < 8; k++) { c0 += red[b*16 + k]; c1 += red[b*16 + 8 + k]; }
        float r0 = __fdividef(1.f, c0), r1 = __fdividef(1.f, c1);
        float be0 = s0 * r0, be1 = s1 * r1;                // scaled beta_t
        out0[(size_t)t*Kk] = pp0 * be0;                    // unnormalized gamma
        out1[(size_t)t*Kk] = pp1 * be1;
        float y0 = be0 * bb0, y1 = be1 * bb1;
        es[tid] = y0; es[Kk + tid] = y1;
        float q0 = y0, q1 = y1; wred2(q0, q1);
        b ^= 1;
        if (!l) { red[b*16 + wi] = q0; red[b*16 + 8 + wi] = q1; }
        __syncthreads();
    }
}

// ---------------- epilogue: per-(n,t) log-normalize ----------------
__global__ void __launch_bounds__(256)
norm_gamma(float* __restrict__ out) {
    int row  = (blockIdx.x << 3) + (threadIdx.x >> 5);
    int lane = threadIdx.x & 31;
    float4* p = reinterpret_cast<float4*>(out + (size_t)row * Kk);
    float4 v0 = p[lane], v1 = p[lane + 32];
    float s = v0.x + v0.y + v0.z + v0.w + v1.x + v1.y + v1.z + v1.w;
    #pragma unroll
    for (int o = 16; o; o >>= 1) s += __shfl_xor_sync(0xFFFFFFFFu, s, o);
    float lc = __logf(s);
    v0.x = __logf(v0.x) - lc; v0.y = __logf(v0.y) - lc;
    v0.z = __logf(v0.z) - lc; v0.w = __logf(v0.w) - lc;
    v1.x = __logf(v1.x) - lc; v1.y = __logf(v1.y) - lc;
    v1.z = __logf(v1.z) - lc; v1.w = __logf(v1.w) - lc;
    p[lane] = v0; p[lane + 32] = v1;
}

// ---------------- launch ----------------
extern "C" void kernel_launch(void* const* d_in, const int* in_sizes, int n_in,
                              void* d_out, int out_size) {
    const float* log_pi = (const float*)d_in[0];
    const float* log_A  = (const float*)d_in[1];
    const float* log_B  = (const float*)d_in[2];
    const int*   observ = (const int*)  d_in[3];
    float* out = (float*)d_out;

    const int smem_bytes = 64*NT*8 + (2*Kk + 2048 + 32)*4 + 2*Tt*4;
    cudaFuncSetAttribute(hmm_fb, cudaFuncAttributeMaxDynamicSharedMemorySize, smem_bytes);

    prep_pack<<<128, 256>>>(log_A, log_pi);
    prep_B<<<(Kk*Vv + 255)/256, 256>>>(log_B);
    hmm_fb<<<NC, NT, smem_bytes>>>(observ, out);
    norm_gamma<<<(NBb*Tt)/8, 256>>>(out);
}

// round 7
// speedup vs baseline: 2.4311x; 1.1088x over previous
#include <cuda_runtime.h>
#include <math.h>
#include <stdint.h>

#define Kk 256
#define Tt 512
#define NBb 256
#define Vv 4096

#define NT 256
#define NC (NBb/2)      // 128 CTAs, 2 sequences each

// Warp tiling: 8 warps = 2 (state dim, p) x 4 (i dim, q).
// Warp (p,q): states {128p + 32m + lane, m=0..3}, i in [64q, 64q+64).
// Per thread: 4 states x 64 i = 128 u64 pairs; 72 in registers (c=0..17 per
// state), 56 via smem (c=18..31). Warp (p,q) also slice-sums seq p's e-slice
// for the (approximate-is-fine) per-step rescale.

typedef unsigned long long ull;

// ---------------- device scratch ----------------
__device__ ull  g_Freg[72*NT];     // forward  A-pack, register part
__device__ ull  g_Fsm [56*NT];     // forward  A-pack, smem part
__device__ ull  g_Breg[72*NT];     // backward A-pack, register part
__device__ ull  g_Bsm [56*NT];     // backward A-pack, smem part
__device__ float g_Bt[Vv*Kk];      // exp(log_B) transposed: [v][j]
__device__ float g_pi[Kk];

// ---------------- prep ----------------
__global__ void prep_pack(const float* __restrict__ logA, const float* __restrict__ logpi) {
    int idx = blockIdx.x * blockDim.x + threadIdx.x;   // 0 .. 32767
    if (idx < Kk) g_pi[idx] = expf(logpi[idx]);
    int tid = idx & 255;
    int k   = idx >> 8;            // 0..127 : k = m*32 + c
    int m = k >> 5, c = k & 31;
    int wi = tid >> 5, l = tid & 31;
    int p = wi >> 2, q = wi & 3;
    int j = 128*p + 32*m + l;      // output state
    int i = 64*q + 2*c;            // summation index (pair base)
    float f0 = expf(logA[i*Kk + j]);        // fwd: sum_i e[i]*A[i][j]
    float f1 = expf(logA[(i+1)*Kk + j]);
    float b0 = expf(logA[j*Kk + i]);        // bwd: sum_i e[i]*A[j][i]
    float b1 = expf(logA[j*Kk + i + 1]);
    ull fv = ((ull)__float_as_uint(f1) << 32) | __float_as_uint(f0);
    ull bv = ((ull)__float_as_uint(b1) << 32) | __float_as_uint(b0);
    if (c < 18) {
        g_Freg[(m*18 + c)*NT + tid] = fv;
        g_Breg[(m*18 + c)*NT + tid] = bv;
    } else {
        int cc = c - 18;
        int u = (((m*7 + (cc>>1))*NT + tid) << 1) | (cc & 1);  // ulonglong2-friendly
        g_Fsm[u] = fv;
        g_Bsm[u] = bv;
    }
}

__global__ void prep_B(const float* __restrict__ logB) {
    int idx = blockIdx.x * blockDim.x + threadIdx.x;   // j*Vv + v (coalesced read)
    if (idx >= Kk*Vv) return;
    int j = idx / Vv, v = idx % Vv;
    g_Bt[v*Kk + j] = expf(logB[idx]);
}

// ---------------- helpers ----------------
__device__ __forceinline__ void ffma2(ull& d, ull a, ull b) {
    asm("fma.rn.f32x2 %0, %1, %2, %0;" : "+l"(d) : "l"(a), "l"(b));
}
__device__ __forceinline__ void fadd2(ull& d, ull a) {
    asm("add.rn.f32x2 %0, %0, %1;" : "+l"(d) : "l"(a));
}
__device__ __forceinline__ float psum1(ull a) {
    unsigned lo, hi; asm("mov.b64 {%0,%1}, %2;" : "=r"(lo), "=r"(hi) : "l"(a));
    return __uint_as_float(lo) + __uint_as_float(hi);
}

// split-K dot: this warp covers i in [64q,64q+64) for its 4 states, both seqs.
// Warp (p,q) also accumulates the slice-sum of seq p's e-slice -> ssum[p*4+q].
__device__ __forceinline__ void do_dot(const ull (&ra)[72],
                                       const ull* __restrict__ As2,
                                       const float* __restrict__ es,   // [2][Kk]
                                       float* __restrict__ part,       // [2][4][256]
                                       float* __restrict__ ssum,       // [2][4]
                                       int p, int q, int l, int tid) {
    const ulonglong2* e0 = reinterpret_cast<const ulonglong2*>(es + 64*q);
    const ulonglong2* e1 = reinterpret_cast<const ulonglong2*>(es + Kk + 64*q);
    ull acc[4][2] = {};
    ull cs = 0;
    // register half: e pairs 0..17 (ulonglong2 0..8)
    #pragma unroll
    for (int h = 0; h < 9; h++) {
        ulonglong2 v0 = e0[h], v1 = e1[h];
        if (p == 0) { fadd2(cs, v0.x); fadd2(cs, v0.y); }
        else        { fadd2(cs, v1.x); fadd2(cs, v1.y); }
        #pragma unroll
        for (int m = 0; m < 4; m++) {
            ffma2(acc[m][0], ra[m*18 + 2*h],     v0.x);
            ffma2(acc[m][0], ra[m*18 + 2*h + 1], v0.y);
            ffma2(acc[m][1], ra[m*18 + 2*h],     v1.x);
            ffma2(acc[m][1], ra[m*18 + 2*h + 1], v1.y);
        }
    }
    // smem half: e pairs 18..31 (ulonglong2 9..15)
    const ulonglong2* Asv = reinterpret_cast<const ulonglong2*>(As2);
    #pragma unroll
    for (int h = 0; h < 7; h++) {
        ulonglong2 v0 = e0[9 + h], v1 = e1[9 + h];
        if (p == 0) { fadd2(cs, v0.x); fadd2(cs, v0.y); }
        else        { fadd2(cs, v1.x); fadd2(cs, v1.y); }
        #pragma unroll
        for (int m = 0; m < 4; m++) {
            ulonglong2 av = Asv[(m*7 + h)*NT + tid];
            ffma2(acc[m][0], av.x, v0.x);
            ffma2(acc[m][0], av.y, v0.y);
            ffma2(acc[m][1], av.x, v1.x);
            ffma2(acc[m][1], av.y, v1.y);
        }
    }
    #pragma unroll
    for (int m = 0; m < 4; m++) {
        int j = 128*p + 32*m + l;
        part[q*256 + j]        = psum1(acc[m][0]);
        part[1024 + q*256 + j] = psum1(acc[m][1]);
    }
    if (l == 0) ssum[p*4 + q] = psum1(cs);
}

// ---------------- main persistent kernel ----------------
__global__ void __launch_bounds__(NT, 1)
hmm_fb(const int* __restrict__ obs, float* __restrict__ out) {
    extern __shared__ float sm[];
    ull*   As2   = (ull*)sm;                    // 56*NT u64 = 112KB
    float* es    = (float*)(As2 + 56*NT);       // [2][Kk]
    float* part  = es + 2*Kk;                   // [2][4][256] = 2048
    float* ssum  = part + 2048;                 // [2][4]
    int*   obs_s = (int*)(ssum + 8);            // [2][Tt]

    const int tid = threadIdx.x, wi = tid >> 5, l = tid & 31;
    const int p = wi >> 2, q = wi & 3;
    const int n0 = 2*blockIdx.x, n1 = n0 + 1;

    for (int i = tid; i < Tt; i += NT) {
        obs_s[i]      = obs[n0*Tt + i];
        obs_s[Tt + i] = obs[n1*Tt + i];
    }

    ull ra[72];
    #pragma unroll
    for (int k = 0; k < 72; k++) ra[k] = g_Freg[k*NT + tid];
    {
        const ulonglong2* src = reinterpret_cast<const ulonglong2*>(g_Fsm);
        ulonglong2*       dst = reinterpret_cast<ulonglong2*>(As2);
        #pragma unroll
        for (int k = 0; k < 28; k++) dst[k*NT + tid] = src[k*NT + tid];
    }

    float* out0 = out + (size_t)n0*Tt*Kk + tid;
    float* out1 = out + (size_t)n1*Tt*Kk + tid;

    float w0, w1;

    // ---- forward init (t = 0) ----
    {
        float pi = g_pi[tid];
        w0 = pi * g_Bt[obs_s[0]  * Kk + tid];
        w1 = pi * g_Bt[obs_s[Tt] * Kk + tid];
        es[tid] = w0; es[Kk + tid] = w1;
        __syncthreads();    // es + A-cache published
    }

    // ---- forward loop ----
    for (int t = 1; t < Tt; t++) {
        float bb0 = g_Bt[obs_s[t]      * Kk + tid];
        float bb1 = g_Bt[obs_s[Tt + t] * Kk + tid];
        do_dot(ra, As2, es, part, ssum, p, q, l, tid);
        __syncthreads();                                   // part + ssum ready
        float4 cv0 = *reinterpret_cast<const float4*>(ssum);
        float4 cv1 = *reinterpret_cast<const float4*>(ssum + 4);
        float s0 = 0.f, s1 = 0.f;
        #pragma unroll
        for (int k = 0; k < 4; k++) { s0 += part[k*256 + tid]; s1 += part[1024 + k*256 + tid]; }
        float r0 = __fdividef(1.f, (cv0.x + cv0.y) + (cv0.z + cv0.w));
        float r1 = __fdividef(1.f, (cv1.x + cv1.y) + (cv1.z + cv1.w));
        out0[(size_t)(t-1)*Kk] = w0 * r0;                  // scale need not be exact
        out1[(size_t)(t-1)*Kk] = w1 * r1;
        w0 = s0 * r0 * bb0;
        w1 = s1 * r1 * bb1;
        es[tid] = w0; es[Kk + tid] = w1;
        __syncthreads();                                   // es ready for next dot
    }
    // last row: any per-row scale works (epilogue renormalizes)
    out0[(size_t)(Tt-1)*Kk] = w0;
    out1[(size_t)(Tt-1)*Kk] = w1;
    __syncthreads();

    // ---- reload A-pack for backward ----
    #pragma unroll
    for (int k = 0; k < 72; k++) ra[k] = g_Breg[k*NT + tid];
    {
        const ulonglong2* src = reinterpret_cast<const ulonglong2*>(g_Bsm);
        ulonglong2*       dst = reinterpret_cast<ulonglong2*>(As2);
        #pragma unroll
        for (int k = 0; k < 28; k++) dst[k*NT + tid] = src[k*NT + tid];
    }

    // ---- backward init: y_{T-1} = B[:,o_{T-1}] (beta = 1) ----
    {
        float y0 = g_Bt[obs_s[Tt-1]      * Kk + tid];
        float y1 = g_Bt[obs_s[Tt + Tt-1] * Kk + tid];
        es[tid] = y0; es[Kk + tid] = y1;
        __syncthreads();
    }

    // ---- backward loop ----
    for (int t = Tt - 2; t >= 0; t--) {
        float pp0 = out0[(size_t)t*Kk];                    // prefetch p_t
        float pp1 = out1[(size_t)t*Kk];
        float bb0 = g_Bt[obs_s[t]      * Kk + tid];
        float bb1 = g_Bt[obs_s[Tt + t] * Kk + tid];
        do_dot(ra, As2, es, part, ssum, p, q, l, tid);
        __syncthreads();
        float4 cv0 = *reinterpret_cast<const float4*>(ssum);
        float4 cv1 = *reinterpret_cast<const float4*>(ssum + 4);
        float s0 = 0.f, s1 = 0.f;
        #pragma unroll
        for (int k = 0; k < 4; k++) { s0 += part[k*256 + tid]; s1 += part[1024 + k*256 + tid]; }
        float r0 = __fdividef(1.f, (cv0.x + cv0.y) + (cv0.z + cv0.w));
        float r1 = __fdividef(1.f, (cv1.x + cv1.y) + (cv1.z + cv1.w));
        float be0 = s0 * r0, be1 = s1 * r1;                // scaled beta_t
        out0[(size_t)t*Kk] = pp0 * be0;                    // unnormalized gamma
        out1[(size_t)t*Kk] = pp1 * be1;
        float y0 = be0 * bb0, y1 = be1 * bb1;
        es[tid] = y0; es[Kk + tid] = y1;
        __syncthreads();
    }
}

// ---------------- epilogue: per-(n,t) log-normalize ----------------
__global__ void __launch_bounds__(256)
norm_gamma(float* __restrict__ out) {
    int row  = (blockIdx.x << 3) + (threadIdx.x >> 5);
    int lane = threadIdx.x & 31;
    float4* p = reinterpret_cast<float4*>(out + (size_t)row * Kk);
    float4 v0 = p[lane], v1 = p[lane + 32];
    float s = v0.x + v0.y + v0.z + v0.w + v1.x + v1.y + v1.z + v1.w;
    #pragma unroll
    for (int o = 16; o; o >>= 1) s += __shfl_xor_sync(0xFFFFFFFFu, s, o);
    float lc = __logf(s);
    v0.x = __logf(v0.x) - lc; v0.y = __logf(v0.y) - lc;
    v0.z = __logf(v0.z) - lc; v0.w = __logf(v0.w) - lc;
    v1.x = __logf(v1.x) - lc; v1.y = __logf(v1.y) - lc;
    v1.z = __logf(v1.z) - lc; v1.w = __logf(v1.w) - lc;
    p[lane] = v0; p[lane + 32] = v1;
}

// ---------------- launch ----------------
extern "C" void kernel_launch(void* const* d_in, const int* in_sizes, int n_in,
                              void* d_out, int out_size) {
    const float* log_pi = (const float*)d_in[0];
    const float* log_A  = (const float*)d_in[1];
    const float* log_B  = (const float*)d_in[2];
    const int*   observ = (const int*)  d_in[3];
    float* out = (float*)d_out;

    const int smem_bytes = 56*NT*8 + (2*Kk + 2048 + 8)*4 + 2*Tt*4;
    cudaFuncSetAttribute(hmm_fb, cudaFuncAttributeMaxDynamicSharedMemorySize, smem_bytes);

    prep_pack<<<128, 256>>>(log_A, log_pi);
    prep_B<<<(Kk*Vv + 255)/256, 256>>>(log_B);
    hmm_fb<<<NC, NT, smem_bytes>>>(observ, out);
    norm_gamma<<<(NBb*Tt)/8, 256>>>(out);
}